// round 5
// baseline (speedup 1.0000x reference)
#include <cuda_runtime.h>
#include <cstdint>

// Problem constants
#define D_DIM 4096
#define E_DIM 64

// Tiling
#define BM 64
#define BN 64
#define BK 32
#define TM 4
#define TN 4
#define NTHREADS 256
#define KTILES (D_DIM / BK)   // 128

// packed f32x2 FMA: d = a*b + d  (two independent fp32 FMAs per instruction)
#define FMA2(d, a, b) \
    asm("fma.rn.f32x2 %0, %1, %2, %3;" : "=l"(d) : "l"(a), "l"(b), "l"(d))

__device__ __forceinline__ bool better(float v, int i, float w, int j) {
    // jax.lax.top_k: larger value wins; ties -> smaller index first
    return (v > w) || (v == w && i < j);
}

__global__ __launch_bounds__(NTHREADS)
void topk_gate_kernel(const float* __restrict__ x,
                      const float* __restrict__ Wm,
                      const float* __restrict__ bias,
                      float* __restrict__ out,
                      int N, int writeIdx)
{
    // Shared memory: two double-buffered tiles (As, Ws) as float4[2][8][65]
    // (padded to 65 to kill STS bank conflicts), then aliased as the logits
    // buffer Ls[64][65] for the epilogue.
    __shared__ __align__(16) unsigned char smem_raw[2 * 2 * 8 * 65 * 16];
    float4* As_base = reinterpret_cast<float4*>(smem_raw);                  // [2][8][65]
    float4* Ws_base = reinterpret_cast<float4*>(smem_raw + 2 * 8 * 65 * 16); // [2][8][65]
    float*  Ls      = reinterpret_cast<float*>(smem_raw);                   // [64][65]

    const int tid  = threadIdx.x;
    const int rowBase = blockIdx.x * BM;

    // compute-thread mapping: tx -> expert group, ty -> row group
    const int tx = tid & 15;        // 0..15 -> experts tx*4 .. tx*4+3
    const int ty = tid >> 4;        // 0..15 -> rows    ty*4 .. ty*4+3
    const int row0 = ty * TM;
    const int col0 = tx * TN;

#define AS(buf, k4, m) As_base[(buf) * 520 + (k4) * 65 + (m)]
#define WS(buf, k4, e) Ws_base[(buf) * 520 + (k4) * 65 + (e)]

    // accumulators: per (i,j) two packed f32x2 lanes (k%4==0,1 and k%4==2,3)
    unsigned long long accA[TM * TN];
    unsigned long long accB[TM * TN];
#pragma unroll
    for (int i = 0; i < TM * TN; i++) { accA[i] = 0ULL; accB[i] = 0ULL; }

    // global-load staging registers: 2 float4 from x, 2 from W per tile
    float4 xa[2], wa[2];
    // load indices: i = tid + s*256 -> r = i>>3 (0..63), k4 = i&7
    const int r0 = tid >> 3;          // s = 0
    const int k4_0 = tid & 7;
    const int r1 = (tid + 256) >> 3;  // s = 1
    const int k4_1 = (tid + 256) & 7;

    // ---- prefetch tile 0 ----
    {
        const int kbase = 0;
        xa[0] = *reinterpret_cast<const float4*>(&x[(size_t)(rowBase + r0) * D_DIM + kbase + k4_0 * 4]);
        xa[1] = *reinterpret_cast<const float4*>(&x[(size_t)(rowBase + r1) * D_DIM + kbase + k4_1 * 4]);
        wa[0] = *reinterpret_cast<const float4*>(&Wm[(size_t)r0 * D_DIM + kbase + k4_0 * 4]);
        wa[1] = *reinterpret_cast<const float4*>(&Wm[(size_t)r1 * D_DIM + kbase + k4_1 * 4]);
        AS(0, k4_0, r0) = xa[0];
        AS(0, k4_1, r1) = xa[1];
        WS(0, k4_0, r0) = wa[0];
        WS(0, k4_1, r1) = wa[1];
    }
    __syncthreads();

    for (int t = 0; t < KTILES; t++) {
        const int buf = t & 1;
        // prefetch next tile from global while computing this one
        if (t + 1 < KTILES) {
            const int kbase = (t + 1) * BK;
            xa[0] = *reinterpret_cast<const float4*>(&x[(size_t)(rowBase + r0) * D_DIM + kbase + k4_0 * 4]);
            xa[1] = *reinterpret_cast<const float4*>(&x[(size_t)(rowBase + r1) * D_DIM + kbase + k4_1 * 4]);
            wa[0] = *reinterpret_cast<const float4*>(&Wm[(size_t)r0 * D_DIM + kbase + k4_0 * 4]);
            wa[1] = *reinterpret_cast<const float4*>(&Wm[(size_t)r1 * D_DIM + kbase + k4_1 * 4]);
        }

        // compute on buf
#pragma unroll
        for (int k4 = 0; k4 < 8; k4++) {
            ulonglong2 a2[TM], w2[TN];
#pragma unroll
            for (int i = 0; i < TM; i++)
                a2[i] = *reinterpret_cast<const ulonglong2*>(&AS(buf, k4, row0 + i));
#pragma unroll
            for (int j = 0; j < TN; j++)
                w2[j] = *reinterpret_cast<const ulonglong2*>(&WS(buf, k4, col0 + j));
#pragma unroll
            for (int i = 0; i < TM; i++) {
#pragma unroll
                for (int j = 0; j < TN; j++) {
                    FMA2(accA[i * TN + j], a2[i].x, w2[j].x);
                    FMA2(accB[i * TN + j], a2[i].y, w2[j].y);
                }
            }
        }

        if (t + 1 < KTILES) {
            const int nbuf = (t + 1) & 1;
            AS(nbuf, k4_0, r0) = xa[0];
            AS(nbuf, k4_1, r1) = xa[1];
            WS(nbuf, k4_0, r0) = wa[0];
            WS(nbuf, k4_1, r1) = wa[1];
        }
        __syncthreads();
    }

    // ---- epilogue: finalize logits, write to Ls ----
#pragma unroll
    for (int j = 0; j < TN; j++) {
        const float bj = bias[col0 + j];
#pragma unroll
        for (int i = 0; i < TM; i++) {
            unsigned long long ua = accA[i * TN + j];
            unsigned long long ub = accB[i * TN + j];
            float s = __int_as_float((int)(ua & 0xffffffffULL))
                    + __int_as_float((int)(ua >> 32))
                    + __int_as_float((int)(ub & 0xffffffffULL))
                    + __int_as_float((int)(ub >> 32));
            Ls[(row0 + i) * 65 + (col0 + j)] = s + bj;
        }
    }
    __syncthreads();

    // ---- top-2 + softmax + scatter; 8 warps x 8 rows each ----
    const int wid  = tid >> 5;
    const int lane = tid & 31;
    const unsigned FULL = 0xffffffffu;

    for (int rr = 0; rr < 8; rr++) {
        const int r = wid * 8 + rr;
        float v0 = Ls[r * 65 + lane];        int i0 = lane;
        float v1 = Ls[r * 65 + lane + 32];   int i1 = lane + 32;
        // local order
        float a1v, a2v; int a1i, a2i;
        if (better(v0, i0, v1, i1)) { a1v = v0; a1i = i0; a2v = v1; a2i = i1; }
        else                        { a1v = v1; a1i = i1; a2v = v0; a2i = i0; }

#pragma unroll
        for (int off = 16; off > 0; off >>= 1) {
            float b1v = __shfl_xor_sync(FULL, a1v, off);
            int   b1i = __shfl_xor_sync(FULL, a1i, off);
            float b2v = __shfl_xor_sync(FULL, a2v, off);
            int   b2i = __shfl_xor_sync(FULL, a2i, off);
            if (better(a1v, a1i, b1v, b1i)) {
                // first stays; second = better(a2, b1)
                if (!better(a2v, a2i, b1v, b1i)) { a2v = b1v; a2i = b1i; }
            } else {
                // b1 wins; second = better(a1, b2)
                if (better(a1v, a1i, b2v, b2i)) { a2v = a1v; a2i = a1i; }
                else                            { a2v = b2v; a2i = b2i; }
                a1v = b1v; a1i = b1i;
            }
        }

        // softmax over the two selected logits (a1v >= a2v)
        float e  = expf(a2v - a1v);
        float d  = 1.0f / (1.0f + e);
        float p1 = d;
        float p2 = e * d;

        const int grow = rowBase + r;
        float g0 = (lane      == a1i) ? p1 : ((lane      == a2i) ? p2 : 0.0f);
        float g1 = (lane + 32 == a1i) ? p1 : ((lane + 32 == a2i) ? p2 : 0.0f);
        out[(size_t)grow * E_DIM + lane]      = g0;
        out[(size_t)grow * E_DIM + lane + 32] = g1;

        if (writeIdx && lane == 0) {
            float* oi = out + (size_t)N * E_DIM;
            oi[(size_t)grow * 2 + 0] = (float)a1i;
            oi[(size_t)grow * 2 + 1] = (float)a2i;
        }
    }
}

extern "C" void kernel_launch(void* const* d_in, const int* in_sizes, int n_in,
                              void* d_out, int out_size)
{
    const float* x  = (const float*)d_in[0];
    const float* Wm = (const float*)d_in[1];
    const float* b  = (const float*)d_in[2];
    float* out = (float*)d_out;

    const int N = in_sizes[0] / D_DIM;          // 16384
    const int writeIdx = (out_size >= N * E_DIM + 2 * N) ? 1 : 0;

    dim3 grid(N / BM);
    dim3 block(NTHREADS);
    topk_gate_kernel<<<grid, block>>>(x, Wm, b, out, N, writeIdx);
}

// round 10
// speedup vs baseline: 4.4270x; 4.4270x over previous
#include <cuda_runtime.h>
#include <cstdint>

// Problem constants
#define D_DIM 4096
#define E_DIM 64
#define BM 128
#define BK 32
#define NTHREADS 256
#define KTILES (D_DIM / BK)   // 128
#define NSTAGE 4

// ---------------- smem layout (dynamic, bytes) ----------------
// per stage: A [128 rows][36 floats] (stride 36 -> conflict-free frag LDS) + B frag-ordered tf32
#define A_STRIDE_F 36
#define A_TILE_BYTES (BM * A_STRIDE_F * 4)      // 18432
#define B_TILE_BYTES (4 * 8 * 64 * 4)           // 8192
#define STAGE_BYTES (A_TILE_BYTES + B_TILE_BYTES)  // 26624
#define SMEM_TOTAL (NSTAGE * STAGE_BYTES)          // 106496
#define LS_STRIDE 65
#define TAU 4e-3f
#define FIX_CAP 16384

// W as tf32 (rna) in mma B-fragment order: [kb(512)][nb(8)][lane(32)][2]
__device__ float g_Wf[512 * 8 * 64];   // 1 MB
__device__ int   g_fix_count;
__device__ int   g_fix_rows[FIX_CAP];

__device__ __forceinline__ uint32_t cvt_tf32_u(float v) {
    uint32_t r;
    asm("cvt.rna.tf32.f32 %0, %1;" : "=r"(r) : "f"(v));
    return r;
}
__device__ __forceinline__ void cp_async16(void* dst, const void* src) {
    uint32_t d;
    asm("{ .reg .u64 t; cvta.to.shared.u64 t, %1; cvt.u32.u64 %0, t; }" : "=r"(d) : "l"(dst));
    asm volatile("cp.async.cg.shared.global [%0], [%1], 16;" :: "r"(d), "l"(src) : "memory");
}
__device__ __forceinline__ bool better(float v, int i, float w, int j) {
    return (v > w) || (v == w && i < j);
}

#define MMA_TF32(C, A, b0, b1)                                              \
    asm volatile("mma.sync.aligned.m16n8k8.row.col.f32.tf32.tf32.f32 "      \
                 "{%0,%1,%2,%3}, {%4,%5,%6,%7}, {%8,%9}, {%0,%1,%2,%3};"    \
                 : "+f"((C)[0]), "+f"((C)[1]), "+f"((C)[2]), "+f"((C)[3])   \
                 : "r"((A)[0]), "r"((A)[1]), "r"((A)[2]), "r"((A)[3]),      \
                   "r"(b0), "r"(b1))

// ---------------- prep: W -> tf32 B-fragments; reset fixup counter ----------------
__global__ void prep_w_kernel(const float* __restrict__ W) {
    const int idx = blockIdx.x * blockDim.x + threadIdx.x;   // 0 .. 131071
    if (idx == 0) g_fix_count = 0;
    if (idx >= 512 * 8 * 32) return;
    const int lane = idx & 31;
    const int nb   = (idx >> 5) & 7;
    const int kb   = idx >> 8;
    const int n = nb * 8 + (lane >> 2);
#pragma unroll
    for (int j = 0; j < 2; j++) {
        const int k = kb * 8 + (lane & 3) + j * 4;
        float w = W[(size_t)n * D_DIM + k];
        g_Wf[(size_t)idx * 2 + j] = __uint_as_float(cvt_tf32_u(w));
    }
}

// ---------------- main fused GEMM + top-2 gate (tf32 fast path) ----------------
__global__ __launch_bounds__(NTHREADS, 1)
void gate_mma_kernel(const float* __restrict__ x,
                     const float* __restrict__ bias,
                     float* __restrict__ out,
                     int N, int writeIdx)
{
    extern __shared__ __align__(16) char smem[];
    float* smemf = reinterpret_cast<float*>(smem);
    __shared__ float sbias[E_DIM];

    const int tid  = threadIdx.x;
    const int wid  = tid >> 5;
    const int lane = tid & 31;
    const int rowBase = blockIdx.x * BM;

    if (tid < E_DIM) sbias[tid] = bias[tid];

    const int mw = wid >> 1;     // 0..3 : rows mw*32..+32
    const int nw = wid & 1;      // 0..1 : cols nw*32..+32
    const int qr = lane >> 2;    // 0..7
    const int qc = lane & 3;     // 0..3

    float acc[2][4][4];
#pragma unroll
    for (int mt = 0; mt < 2; mt++)
#pragma unroll
        for (int nt = 0; nt < 4; nt++)
#pragma unroll
            for (int i = 0; i < 4; i++) acc[mt][nt][i] = 0.0f;

    const float* xbase = x + (size_t)rowBase * D_DIM;

    auto load_stage = [&](int t) {
        const int s = t & (NSTAGE - 1);
        char* abuf = smem + s * STAGE_BYTES;
        char* bbuf = abuf + A_TILE_BYTES;
        const int kb0 = t * BK;
        const float* bsrc = g_Wf + (size_t)t * 2048;
#pragma unroll
        for (int i = 0; i < 4; i++) {           // A: 1024 16B granules
            const int g = tid + i * 256;
            const int r = g >> 3, k4 = g & 7;
            cp_async16(abuf + r * (A_STRIDE_F * 4) + k4 * 16,
                       xbase + (size_t)r * D_DIM + kb0 + k4 * 4);
        }
#pragma unroll
        for (int i = 0; i < 2; i++) {           // B: 512 16B granules
            const int g = tid + i * 256;
            cp_async16(bbuf + g * 16, bsrc + g * 4);
        }
        asm volatile("cp.async.commit_group;" ::: "memory");
    };

    load_stage(0);
    load_stage(1);

    for (int t = 0; t < KTILES; t++) {
        if (t + 2 < KTILES) {
            load_stage(t + 2);
            asm volatile("cp.async.wait_group 2;" ::: "memory");
        } else if (t + 1 < KTILES) {
            asm volatile("cp.async.wait_group 1;" ::: "memory");
        } else {
            asm volatile("cp.async.wait_group 0;" ::: "memory");
        }
        __syncthreads();

        const int s = t & (NSTAGE - 1);
        const float* As = smemf + (s * STAGE_BYTES) / 4;
        const float* Bs = As + A_TILE_BYTES / 4;

#pragma unroll
        for (int kk = 0; kk < 4; kk++) {
            const int k0 = kk * 8;
            uint32_t af[2][4];
#pragma unroll
            for (int mt = 0; mt < 2; mt++) {
                const int r = mw * 32 + mt * 16 + qr;
                af[mt][0] = cvt_tf32_u(As[(r    ) * A_STRIDE_F + k0 + qc    ]);
                af[mt][1] = cvt_tf32_u(As[(r + 8) * A_STRIDE_F + k0 + qc    ]);
                af[mt][2] = cvt_tf32_u(As[(r    ) * A_STRIDE_F + k0 + qc + 4]);
                af[mt][3] = cvt_tf32_u(As[(r + 8) * A_STRIDE_F + k0 + qc + 4]);
            }
#pragma unroll
            for (int nt = 0; nt < 4; nt++) {
                const int nb = nw * 4 + nt;
                const float2 bf = *reinterpret_cast<const float2*>(
                    Bs + ((kk * 8 + nb) * 64 + lane * 2));
                const uint32_t b0 = __float_as_uint(bf.x), b1 = __float_as_uint(bf.y);
                MMA_TF32(acc[0][nt], af[0], b0, b1);
                MMA_TF32(acc[1][nt], af[1], b0, b1);
            }
        }
    }
    __syncthreads();

    // ---- accumulators -> smem logits [128][65] ----
    float* Ls = smemf;
#pragma unroll
    for (int mt = 0; mt < 2; mt++) {
#pragma unroll
        for (int nt = 0; nt < 4; nt++) {
            const int r0 = mw * 32 + mt * 16 + qr;
            const int c0 = nw * 32 + nt * 8 + qc * 2;
            Ls[(r0    ) * LS_STRIDE + c0    ] = acc[mt][nt][0];
            Ls[(r0    ) * LS_STRIDE + c0 + 1] = acc[mt][nt][1];
            Ls[(r0 + 8) * LS_STRIDE + c0    ] = acc[mt][nt][2];
            Ls[(r0 + 8) * LS_STRIDE + c0 + 1] = acc[mt][nt][3];
        }
    }
    __syncthreads();

    // ---- top-3 + softmax + scatter + ambiguity flag: warps 0-3, row per lane ----
    if (wid < 4) {
        const int r = wid * 32 + lane;
        const float* lrow = Ls + r * LS_STRIDE;
        float v1 = -3.4e38f, v2 = -3.4e38f, v3 = -3.4e38f;
        int i1 = 0, i2 = 0, i3 = 0;
#pragma unroll
        for (int j = 0; j < E_DIM; j++) {
            float f = lrow[j] + sbias[j];
            if (better(f, j, v1, i1)) { v3 = v2; i3 = i2; v2 = v1; i2 = i1; v1 = f; i1 = j; }
            else if (better(f, j, v2, i2)) { v3 = v2; i3 = i2; v2 = f; i2 = j; }
            else if (better(f, j, v3, i3)) { v3 = f; i3 = j; }
        }
        float e  = expf(v2 - v1);
        float p1 = 1.0f / (1.0f + e);
        float p2 = e * p1;

        const int grow = rowBase + r;
        float* orow = out + (size_t)grow * E_DIM;
#pragma unroll
        for (int jj = 0; jj < 16; jj++) {
            float4 v;
            const int j0 = jj * 4;
            v.x = (j0     == i1) ? p1 : ((j0     == i2) ? p2 : 0.0f);
            v.y = (j0 + 1 == i1) ? p1 : ((j0 + 1 == i2) ? p2 : 0.0f);
            v.z = (j0 + 2 == i1) ? p1 : ((j0 + 2 == i2) ? p2 : 0.0f);
            v.w = (j0 + 3 == i1) ? p1 : ((j0 + 3 == i2) ? p2 : 0.0f);
            *reinterpret_cast<float4*>(orow + j0) = v;
        }
        if (writeIdx) {
            float2 ix = make_float2((float)i1, (float)i2);
            *reinterpret_cast<float2*>(out + (size_t)N * E_DIM + (size_t)grow * 2) = ix;
        }
        // ambiguous ordering? -> exact fixup
        if ((v1 - v2 < TAU) || (v2 - v3 < TAU)) {
            int pos = atomicAdd(&g_fix_count, 1);
            if (pos < FIX_CAP) g_fix_rows[pos] = grow;
        }
    }
}

// ---------------- fixup: exact fp32 recompute of flagged rows ----------------
__global__ __launch_bounds__(256)
void fix_kernel(const float* __restrict__ x,
                const float* __restrict__ W,
                const float* __restrict__ bias,
                float* __restrict__ out,
                int N, int writeIdx)
{
    __shared__ float4 sx[D_DIM / 4];     // 16 KB
    __shared__ float  sl[E_DIM];
    __shared__ float  sp1, sp2;
    __shared__ int    si1, si2;

    const int tid  = threadIdx.x;
    const int wid  = tid >> 5;
    const int lane = tid & 31;
    const int cnt = min(g_fix_count, FIX_CAP);

    for (int i = blockIdx.x; i < cnt; i += gridDim.x) {
        const int row = g_fix_rows[i];
        const float4* xrow = reinterpret_cast<const float4*>(x + (size_t)row * D_DIM);
        for (int j = tid; j < D_DIM / 4; j += 256) sx[j] = xrow[j];
        __syncthreads();

        for (int e = wid; e < E_DIM; e += 8) {
            const float4* wrow = reinterpret_cast<const float4*>(W + (size_t)e * D_DIM);
            float s = 0.0f;
#pragma unroll 8
            for (int q = 0; q < D_DIM / 4 / 32; q++) {
                float4 a = sx[lane + q * 32];
                float4 b = __ldg(&wrow[lane + q * 32]);
                s += a.x * b.x + a.y * b.y + a.z * b.z + a.w * b.w;
            }
#pragma unroll
            for (int off = 16; off > 0; off >>= 1)
                s += __shfl_xor_sync(0xffffffffu, s, off);
            if (lane == 0) sl[e] = s + bias[e];
        }
        __syncthreads();

        if (tid == 0) {
            float v1 = -3.4e38f, v2 = -3.4e38f;
            int i1 = 0, i2 = 0;
            for (int j = 0; j < E_DIM; j++) {
                float f = sl[j];
                if (better(f, j, v1, i1)) { v2 = v1; i2 = i1; v1 = f; i1 = j; }
                else if (better(f, j, v2, i2)) { v2 = f; i2 = j; }
            }
            float e2 = expf(v2 - v1);
            float p1 = 1.0f / (1.0f + e2);
            sp1 = p1; sp2 = e2 * p1; si1 = i1; si2 = i2;
        }
        __syncthreads();

        if (tid < E_DIM) {
            float g = (tid == si1) ? sp1 : ((tid == si2) ? sp2 : 0.0f);
            out[(size_t)row * E_DIM + tid] = g;
        }
        if (writeIdx && tid == 0) {
            float* oi = out + (size_t)N * E_DIM;
            oi[(size_t)row * 2 + 0] = (float)si1;
            oi[(size_t)row * 2 + 1] = (float)si2;
        }
        __syncthreads();
    }
}

extern "C" void kernel_launch(void* const* d_in, const int* in_sizes, int n_in,
                              void* d_out, int out_size)
{
    const float* x  = (const float*)d_in[0];
    const float* Wm = (const float*)d_in[1];
    const float* b  = (const float*)d_in[2];
    float* out = (float*)d_out;

    const int N = in_sizes[0] / D_DIM;   // 16384
    const int writeIdx = (out_size >= N * E_DIM + 2 * N) ? 1 : 0;

    cudaFuncSetAttribute(gate_mma_kernel,
                         cudaFuncAttributeMaxDynamicSharedMemorySize, SMEM_TOTAL);

    prep_w_kernel<<<512, 256>>>(Wm);
    gate_mma_kernel<<<N / BM, NTHREADS, SMEM_TOTAL>>>(x, b, out, N, writeIdx);
    fix_kernel<<<512, 256>>>(x, Wm, b, out, N, writeIdx);
}

// round 11
// speedup vs baseline: 4.4873x; 1.0136x over previous
#include <cuda_runtime.h>
#include <cstdint>

// Problem constants
#define D_DIM 4096
#define E_DIM 64
#define BM 128
#define BK 64
#define NTHREADS 256
#define KSTAGES (D_DIM / BK)   // 64
#define NSTAGE 3

// ---------------- smem layout (dynamic, bytes) ----------------
// per stage: A [128 rows][68 floats] (stride 68 -> conflict-free frag LDS)
//            B frag-ordered tf32 [kk(8)][nb(8)][lane(32)][2]
#define A_STRIDE_F 68
#define A_TILE_BYTES (BM * A_STRIDE_F * 4)      // 34816
#define B_TILE_BYTES (8 * 8 * 64 * 4)           // 16384
#define STAGE_BYTES (A_TILE_BYTES + B_TILE_BYTES)  // 51200
#define SMEM_TOTAL (NSTAGE * STAGE_BYTES)          // 153600
#define LS_STRIDE 65
#define TAU 4e-3f
#define FIX_CAP 16384

// W as tf32 (rna) in mma B-fragment order: [kb(512)][nb(8)][lane(32)][2]
__device__ float g_Wf[512 * 8 * 64];   // 1 MB
__device__ int   g_fix_count;
__device__ int   g_fix_rows[FIX_CAP];

__device__ __forceinline__ uint32_t cvt_tf32_u(float v) {
    uint32_t r;
    asm("cvt.rna.tf32.f32 %0, %1;" : "=r"(r) : "f"(v));
    return r;
}
__device__ __forceinline__ void cp_async16(void* dst, const void* src) {
    uint32_t d;
    asm("{ .reg .u64 t; cvta.to.shared.u64 t, %1; cvt.u32.u64 %0, t; }" : "=r"(d) : "l"(dst));
    asm volatile("cp.async.cg.shared.global [%0], [%1], 16;" :: "r"(d), "l"(src) : "memory");
}
__device__ __forceinline__ bool better(float v, int i, float w, int j) {
    return (v > w) || (v == w && i < j);
}

#define MMA_TF32(C, A, b0, b1)                                              \
    asm volatile("mma.sync.aligned.m16n8k8.row.col.f32.tf32.tf32.f32 "      \
                 "{%0,%1,%2,%3}, {%4,%5,%6,%7}, {%8,%9}, {%0,%1,%2,%3};"    \
                 : "+f"((C)[0]), "+f"((C)[1]), "+f"((C)[2]), "+f"((C)[3])   \
                 : "r"((A)[0]), "r"((A)[1]), "r"((A)[2]), "r"((A)[3]),      \
                   "r"(b0), "r"(b1))

// ---------------- prep: W -> tf32 B-fragments; reset fixup counter ----------------
__global__ void prep_w_kernel(const float* __restrict__ W) {
    const int idx = blockIdx.x * blockDim.x + threadIdx.x;   // 0 .. 131071
    if (idx == 0) g_fix_count = 0;
    if (idx >= 512 * 8 * 32) return;
    const int lane = idx & 31;
    const int nb   = (idx >> 5) & 7;
    const int kb   = idx >> 8;
    const int n = nb * 8 + (lane >> 2);
#pragma unroll
    for (int j = 0; j < 2; j++) {
        const int k = kb * 8 + (lane & 3) + j * 4;
        float w = W[(size_t)n * D_DIM + k];
        g_Wf[(size_t)idx * 2 + j] = __uint_as_float(cvt_tf32_u(w));
    }
}

// ---------------- main fused GEMM + top-2 gate (tf32 fast path) ----------------
__global__ __launch_bounds__(NTHREADS, 1)
void gate_mma_kernel(const float* __restrict__ x,
                     const float* __restrict__ bias,
                     float* __restrict__ out,
                     int N, int writeIdx)
{
    extern __shared__ __align__(16) char smem[];
    float* smemf = reinterpret_cast<float*>(smem);
    __shared__ float sbias[E_DIM];

    const int tid  = threadIdx.x;
    const int wid  = tid >> 5;
    const int lane = tid & 31;
    const int rowBase = blockIdx.x * BM;

    if (tid < E_DIM) sbias[tid] = bias[tid];

    const int mw = wid >> 1;     // 0..3 : rows mw*32..+32
    const int nw = wid & 1;      // 0..1 : cols nw*32..+32
    const int qr = lane >> 2;    // 0..7
    const int qc = lane & 3;     // 0..3

    float acc[2][4][4];
#pragma unroll
    for (int mt = 0; mt < 2; mt++)
#pragma unroll
        for (int nt = 0; nt < 4; nt++)
#pragma unroll
            for (int i = 0; i < 4; i++) acc[mt][nt][i] = 0.0f;

    const float* xbase = x + (size_t)rowBase * D_DIM;

    auto load_stage = [&](int t) {
        const int s = (t < NSTAGE) ? t : (t % NSTAGE);
        char* abuf = smem + s * STAGE_BYTES;
        char* bbuf = abuf + A_TILE_BYTES;
        const int kb0 = t * BK;
        const float* bsrc = g_Wf + (size_t)t * 4096;
#pragma unroll
        for (int i = 0; i < 8; i++) {           // A: 2048 16B granules
            const int g = tid + i * 256;
            const int r = g >> 4, k4 = g & 15;
            cp_async16(abuf + r * (A_STRIDE_F * 4) + k4 * 16,
                       xbase + (size_t)r * D_DIM + kb0 + k4 * 4);
        }
#pragma unroll
        for (int i = 0; i < 4; i++) {           // B: 1024 16B granules
            const int g = tid + i * 256;
            cp_async16(bbuf + g * 16, bsrc + g * 4);
        }
        asm volatile("cp.async.commit_group;" ::: "memory");
    };

    load_stage(0);
    load_stage(1);

    for (int t = 0; t < KSTAGES; t++) {
        if (t + 2 < KSTAGES) {
            load_stage(t + 2);
            asm volatile("cp.async.wait_group 2;" ::: "memory");
        } else if (t + 1 < KSTAGES) {
            asm volatile("cp.async.wait_group 1;" ::: "memory");
        } else {
            asm volatile("cp.async.wait_group 0;" ::: "memory");
        }
        __syncthreads();

        const int s = t % NSTAGE;
        const float* As = smemf + (s * STAGE_BYTES) / 4;
        const float* Bs = As + A_TILE_BYTES / 4;

        // register software pipeline over kk (8 sub-steps of K=8)
        uint32_t af[2][2][4];
        float    bf[2][4][2];

        // preload kk = 0
        {
            const int k0 = 0;
#pragma unroll
            for (int mt = 0; mt < 2; mt++) {
                const int r = mw * 32 + mt * 16 + qr;
                af[0][mt][0] = cvt_tf32_u(As[(r    ) * A_STRIDE_F + k0 + qc    ]);
                af[0][mt][1] = cvt_tf32_u(As[(r + 8) * A_STRIDE_F + k0 + qc    ]);
                af[0][mt][2] = cvt_tf32_u(As[(r    ) * A_STRIDE_F + k0 + qc + 4]);
                af[0][mt][3] = cvt_tf32_u(As[(r + 8) * A_STRIDE_F + k0 + qc + 4]);
            }
#pragma unroll
            for (int nt = 0; nt < 4; nt++) {
                const int nb = nw * 4 + nt;
                const float2 bfv = *reinterpret_cast<const float2*>(
                    Bs + ((0 * 8 + nb) * 64 + lane * 2));
                bf[0][nt][0] = bfv.x; bf[0][nt][1] = bfv.y;
            }
        }

#pragma unroll
        for (int kk = 0; kk < 8; kk++) {
            const int cur = kk & 1;
            const int nxt = cur ^ 1;
            if (kk < 7) {
                const int k0 = (kk + 1) * 8;
#pragma unroll
                for (int mt = 0; mt < 2; mt++) {
                    const int r = mw * 32 + mt * 16 + qr;
                    af[nxt][mt][0] = cvt_tf32_u(As[(r    ) * A_STRIDE_F + k0 + qc    ]);
                    af[nxt][mt][1] = cvt_tf32_u(As[(r + 8) * A_STRIDE_F + k0 + qc    ]);
                    af[nxt][mt][2] = cvt_tf32_u(As[(r    ) * A_STRIDE_F + k0 + qc + 4]);
                    af[nxt][mt][3] = cvt_tf32_u(As[(r + 8) * A_STRIDE_F + k0 + qc + 4]);
                }
#pragma unroll
                for (int nt = 0; nt < 4; nt++) {
                    const int nb = nw * 4 + nt;
                    const float2 bfv = *reinterpret_cast<const float2*>(
                        Bs + (((kk + 1) * 8 + nb) * 64 + lane * 2));
                    bf[nxt][nt][0] = bfv.x; bf[nxt][nt][1] = bfv.y;
                }
            }
#pragma unroll
            for (int nt = 0; nt < 4; nt++) {
                const uint32_t b0 = __float_as_uint(bf[cur][nt][0]);
                const uint32_t b1 = __float_as_uint(bf[cur][nt][1]);
                MMA_TF32(acc[0][nt], af[cur][0], b0, b1);
                MMA_TF32(acc[1][nt], af[cur][1], b0, b1);
            }
        }
    }
    __syncthreads();

    // ---- accumulators -> smem logits [128][65] ----
    float* Ls = smemf;
#pragma unroll
    for (int mt = 0; mt < 2; mt++) {
#pragma unroll
        for (int nt = 0; nt < 4; nt++) {
            const int r0 = mw * 32 + mt * 16 + qr;
            const int c0 = nw * 32 + nt * 8 + qc * 2;
            Ls[(r0    ) * LS_STRIDE + c0    ] = acc[mt][nt][0];
            Ls[(r0    ) * LS_STRIDE + c0 + 1] = acc[mt][nt][1];
            Ls[(r0 + 8) * LS_STRIDE + c0    ] = acc[mt][nt][2];
            Ls[(r0 + 8) * LS_STRIDE + c0 + 1] = acc[mt][nt][3];
        }
    }
    __syncthreads();

    // ---- top-3 + softmax + scatter + ambiguity flag: warps 0-3, row per lane ----
    if (wid < 4) {
        const int r = wid * 32 + lane;
        const float* lrow = Ls + r * LS_STRIDE;
        float v1 = -3.4e38f, v2 = -3.4e38f, v3 = -3.4e38f;
        int i1 = 0, i2 = 0, i3 = 0;
#pragma unroll
        for (int j = 0; j < E_DIM; j++) {
            float f = lrow[j] + sbias[j];
            if (better(f, j, v1, i1)) { v3 = v2; i3 = i2; v2 = v1; i2 = i1; v1 = f; i1 = j; }
            else if (better(f, j, v2, i2)) { v3 = v2; i3 = i2; v2 = f; i2 = j; }
            else if (better(f, j, v3, i3)) { v3 = f; i3 = j; }
        }
        float e  = expf(v2 - v1);
        float p1 = 1.0f / (1.0f + e);
        float p2 = e * p1;

        const int grow = rowBase + r;
        float* orow = out + (size_t)grow * E_DIM;
#pragma unroll
        for (int jj = 0; jj < 16; jj++) {
            float4 v;
            const int j0 = jj * 4;
            v.x = (j0     == i1) ? p1 : ((j0     == i2) ? p2 : 0.0f);
            v.y = (j0 + 1 == i1) ? p1 : ((j0 + 1 == i2) ? p2 : 0.0f);
            v.z = (j0 + 2 == i1) ? p1 : ((j0 + 2 == i2) ? p2 : 0.0f);
            v.w = (j0 + 3 == i1) ? p1 : ((j0 + 3 == i2) ? p2 : 0.0f);
            *reinterpret_cast<float4*>(orow + j0) = v;
        }
        if (writeIdx) {
            float2 ix = make_float2((float)i1, (float)i2);
            *reinterpret_cast<float2*>(out + (size_t)N * E_DIM + (size_t)grow * 2) = ix;
        }
        // ambiguous ordering? -> exact fixup
        if ((v1 - v2 < TAU) || (v2 - v3 < TAU)) {
            int pos = atomicAdd(&g_fix_count, 1);
            if (pos < FIX_CAP) g_fix_rows[pos] = grow;
        }
    }
}

// ---------------- fixup: exact fp32 recompute of flagged rows ----------------
__global__ __launch_bounds__(256)
void fix_kernel(const float* __restrict__ x,
                const float* __restrict__ W,
                const float* __restrict__ bias,
                float* __restrict__ out,
                int N, int writeIdx)
{
    __shared__ float4 sx[D_DIM / 4];     // 16 KB
    __shared__ float  sl[E_DIM];
    __shared__ float  sp1, sp2;
    __shared__ int    si1, si2;

    const int tid  = threadIdx.x;
    const int wid  = tid >> 5;
    const int lane = tid & 31;
    const int cnt = min(g_fix_count, FIX_CAP);

    for (int i = blockIdx.x; i < cnt; i += gridDim.x) {
        const int row = g_fix_rows[i];
        const float4* xrow = reinterpret_cast<const float4*>(x + (size_t)row * D_DIM);
        for (int j = tid; j < D_DIM / 4; j += 256) sx[j] = xrow[j];
        __syncthreads();

        for (int e = wid; e < E_DIM; e += 8) {
            const float4* wrow = reinterpret_cast<const float4*>(W + (size_t)e * D_DIM);
            float s = 0.0f;
#pragma unroll 8
            for (int q = 0; q < D_DIM / 4 / 32; q++) {
                float4 a = sx[lane + q * 32];
                float4 b = __ldg(&wrow[lane + q * 32]);
                s += a.x * b.x + a.y * b.y + a.z * b.z + a.w * b.w;
            }
#pragma unroll
            for (int off = 16; off > 0; off >>= 1)
                s += __shfl_xor_sync(0xffffffffu, s, off);
            if (lane == 0) sl[e] = s + bias[e];
        }
        __syncthreads();

        if (tid == 0) {
            float v1 = -3.4e38f, v2 = -3.4e38f;
            int i1 = 0, i2 = 0;
            for (int j = 0; j < E_DIM; j++) {
                float f = sl[j];
                if (better(f, j, v1, i1)) { v2 = v1; i2 = i1; v1 = f; i1 = j; }
                else if (better(f, j, v2, i2)) { v2 = f; i2 = j; }
            }
            float e2 = expf(v2 - v1);
            float p1 = 1.0f / (1.0f + e2);
            sp1 = p1; sp2 = e2 * p1; si1 = i1; si2 = i2;
        }
        __syncthreads();

        if (tid < E_DIM) {
            float g = (tid == si1) ? sp1 : ((tid == si2) ? sp2 : 0.0f);
            out[(size_t)row * E_DIM + tid] = g;
        }
        if (writeIdx && tid == 0) {
            float* oi = out + (size_t)N * E_DIM;
            oi[(size_t)row * 2 + 0] = (float)si1;
            oi[(size_t)row * 2 + 1] = (float)si2;
        }
        __syncthreads();
    }
}

extern "C" void kernel_launch(void* const* d_in, const int* in_sizes, int n_in,
                              void* d_out, int out_size)
{
    const float* x  = (const float*)d_in[0];
    const float* Wm = (const float*)d_in[1];
    const float* b  = (const float*)d_in[2];
    float* out = (float*)d_out;

    const int N = in_sizes[0] / D_DIM;   // 16384
    const int writeIdx = (out_size >= N * E_DIM + 2 * N) ? 1 : 0;

    cudaFuncSetAttribute(gate_mma_kernel,
                         cudaFuncAttributeMaxDynamicSharedMemorySize, SMEM_TOTAL);

    prep_w_kernel<<<512, 256>>>(Wm);
    gate_mma_kernel<<<N / BM, NTHREADS, SMEM_TOTAL>>>(x, b, out, N, writeIdx);
    fix_kernel<<<512, 256>>>(x, Wm, b, out, N, writeIdx);
}